// round 1
// baseline (speedup 1.0000x reference)
#include <cuda_runtime.h>
#include <math.h>
#include <limits.h>

#define Nn 30000
#define Ee 400000
#define C1n 15000
#define E2n 100000
#define C2n 7500
#define Bn 16

// ---------------- scratch (device globals: no allocations allowed) ----------
__device__ float g_G1[(size_t)Nn * 800];    // per-node  G1[v, r*32+o] = sum_i x[v,i]*w1b[r,i,o]   (96MB)
__device__ float g_bb1[Nn * 32];            // per-node  sum_i x[v,i]*b1b[i,o]
__device__ float g_sum1[Nn * 32];
__device__ float g_cnt1[Nn];
__device__ float g_xp[C1n * 32];            // seg_max(x1, cluster1)
__device__ float g_possum[C1n * 3];         // seg sum pos -> finalized to posp in place
__device__ float g_poscnt[C1n];
__device__ int   g_batchp[C1n];
__device__ float g_maxabs;
__device__ float g_G2[(size_t)C1n * 1600];  // per-node  G2[v, r*64+o] = sum_i xp[v,i]*w2b[r,i,o]  (96MB)
__device__ float g_bb2[C1n * 64];
__device__ float g_sum2[C1n * 64];
__device__ float g_cnt2[C1n];
__device__ float g_x3[C2n * 64];
__device__ int   g_batch2[C2n];
__device__ float g_gsum[Bn * 64];
__device__ float g_gcnt[Bn];

__device__ __forceinline__ void atomicMaxFloat(float* addr, float val) {
    if (val >= 0.f) atomicMax((int*)addr, __float_as_int(val));
    else            atomicMin((unsigned int*)addr, __float_as_uint(val));
}

__device__ __forceinline__ float elu1(float v) { return v > 0.f ? v : expm1f(v); }

// ---------------- K0: init all accumulators ---------------------------------
__global__ void k_init() {
    int t = blockIdx.x * blockDim.x + threadIdx.x;
    int S = gridDim.x * blockDim.x;
    const float NEGINF = __int_as_float(0xff800000);
    for (int i = t; i < Nn * 32; i += S) g_sum1[i] = 0.f;
    for (int i = t; i < Nn; i += S)      g_cnt1[i] = 0.f;
    for (int i = t; i < C1n * 32; i += S) g_xp[i] = NEGINF;
    for (int i = t; i < C1n * 3; i += S)  g_possum[i] = 0.f;
    for (int i = t; i < C1n; i += S) { g_poscnt[i] = 0.f; g_batchp[i] = INT_MIN; g_cnt2[i] = 0.f; }
    for (int i = t; i < C1n * 64; i += S) g_sum2[i] = 0.f;
    for (int i = t; i < C2n * 64; i += S) g_x3[i] = NEGINF;
    for (int i = t; i < C2n; i += S)      g_batch2[i] = INT_MIN;
    for (int i = t; i < Bn * 64; i += S)  g_gsum[i] = 0.f;
    for (int i = t; i < Bn; i += S)       g_gcnt[i] = 0.f;
    if (t == 0) g_maxabs = 0.f;
}

// ---------------- K1: per-node factor G1 (warp per node) --------------------
__global__ void k_G1(const float* __restrict__ x, const float* __restrict__ w1b,
                     const float* __restrict__ b1b) {
    int v = (blockIdx.x * blockDim.x + threadIdx.x) >> 5;
    int lane = threadIdx.x & 31;
    if (v >= Nn) return;
    float xv[6];
#pragma unroll
    for (int i = 0; i < 6; i++) xv[i] = x[v * 6 + i];
    float* G = g_G1 + (size_t)v * 800;
#pragma unroll 5
    for (int r = 0; r < 25; r++) {
        float acc = 0.f;
#pragma unroll
        for (int i = 0; i < 6; i++) acc = fmaf(xv[i], w1b[r * 192 + i * 32 + lane], acc);
        G[r * 32 + lane] = acc;
    }
    float acc = 0.f;
#pragma unroll
    for (int i = 0; i < 6; i++) acc = fmaf(xv[i], b1b[i * 32 + lane], acc);
    g_bb1[v * 32 + lane] = acc;
}

// ---------------- K2: conv1 edge kernel (warp per edge) ---------------------
__global__ void k_conv1(const float* __restrict__ ea, const int* __restrict__ ei,
                        const float* __restrict__ w1a, const float* __restrict__ b1a) {
    int e = (blockIdx.x * blockDim.x + threadIdx.x) >> 5;
    int lane = threadIdx.x & 31;
    if (e >= Ee) return;
    int src = ei[e], dst = ei[Ee + e];
    float h = 0.f;
    float a0 = ea[e * 3], a1 = ea[e * 3 + 1], a2 = ea[e * 3 + 2];
    if (lane < 25) {
        h = fmaf(a0, w1a[lane], fmaf(a1, w1a[25 + lane], fmaf(a2, w1a[50 + lane], b1a[lane])));
        h = fmaxf(h, 0.f);
    }
    const float* G = g_G1 + (size_t)src * 800;
    float msg = g_bb1[src * 32 + lane];
#pragma unroll
    for (int r = 0; r < 25; r++) {
        float hr = __shfl_sync(0xffffffffu, h, r);
        msg = fmaf(hr, G[r * 32 + lane], msg);
    }
    atomicAdd(&g_sum1[dst * 32 + lane], msg);
    if (lane == 0) atomicAdd(&g_cnt1[dst], 1.f);
}

// ---------------- K3: node update 1 + pool1 scatter (warp per node) ---------
__global__ void k_node1(const float* __restrict__ x, const float* __restrict__ pos,
                        const int* __restrict__ batch, const int* __restrict__ cl1,
                        const float* __restrict__ root1, const float* __restrict__ bias1) {
    int n = (blockIdx.x * blockDim.x + threadIdx.x) >> 5;
    int lane = threadIdx.x & 31;
    if (n >= Nn) return;
    float cnt = fmaxf(g_cnt1[n], 1.f);
    float v = g_sum1[n * 32 + lane] / cnt + bias1[lane];
#pragma unroll
    for (int i = 0; i < 6; i++) v = fmaf(x[n * 6 + i], root1[i * 32 + lane], v);
    float x1 = elu1(v);
    int c = cl1[n];
    atomicMaxFloat(&g_xp[c * 32 + lane], x1);
    if (lane < 3) atomicAdd(&g_possum[c * 3 + lane], pos[n * 3 + lane]);
    if (lane == 0) { atomicAdd(&g_poscnt[c], 1.f); atomicMax(&g_batchp[c], batch[n]); }
}

// ---------------- K4: pool1 finalize ----------------------------------------
__global__ void k_pool1fix() {
    int c = (blockIdx.x * blockDim.x + threadIdx.x) >> 5;
    int lane = threadIdx.x & 31;
    if (c >= C1n) return;
    float v = g_xp[c * 32 + lane];
    if (v < -3e38f) g_xp[c * 32 + lane] = 0.f;   // empty cluster: -inf -> 0
    if (lane < 3) g_possum[c * 3 + lane] = g_possum[c * 3 + lane] / fmaxf(g_poscnt[c], 1.f);
    if (lane == 0) g_batchp[c] = max(g_batchp[c], 0);
}

// ---------------- K5: global max |cart| over E2 edges ------------------------
__global__ void k_maxabs(const int* __restrict__ ei2) {
    int e = blockIdx.x * blockDim.x + threadIdx.x;
    float m = 0.f;
    if (e < E2n) {
        int s = ei2[e], d = ei2[E2n + e];
#pragma unroll
        for (int k = 0; k < 3; k++)
            m = fmaxf(m, fabsf(g_possum[s * 3 + k] - g_possum[d * 3 + k]));
    }
#pragma unroll
    for (int o = 16; o; o >>= 1) m = fmaxf(m, __shfl_xor_sync(0xffffffffu, m, o));
    if ((threadIdx.x & 31) == 0) atomicMax((int*)&g_maxabs, __float_as_int(m));
}

// ---------------- K6: per-node factor G2 (8 nodes per 256-thread block) -----
__global__ void k_G2(const float* __restrict__ w2b, const float* __restrict__ b2b) {
    __shared__ float xs[8][32];
    int vbase = blockIdx.x * 8;
    int tid = threadIdx.x;
    xs[tid >> 5][tid & 31] = g_xp[vbase * 32 + tid];
    __syncthreads();
    for (int col = tid; col < 1600; col += 256) {
        int r = col >> 6, o = col & 63;
        float acc[8] = {0, 0, 0, 0, 0, 0, 0, 0};
#pragma unroll 8
        for (int i = 0; i < 32; i++) {
            float wv = w2b[r * 2048 + i * 64 + o];
#pragma unroll
            for (int v = 0; v < 8; v++) acc[v] = fmaf(xs[v][i], wv, acc[v]);
        }
#pragma unroll
        for (int v = 0; v < 8; v++) g_G2[(size_t)(vbase + v) * 1600 + col] = acc[v];
    }
    for (int o = tid; o < 64; o += 256) {
        float acc[8] = {0, 0, 0, 0, 0, 0, 0, 0};
#pragma unroll 8
        for (int i = 0; i < 32; i++) {
            float wv = b2b[i * 64 + o];
#pragma unroll
            for (int v = 0; v < 8; v++) acc[v] = fmaf(xs[v][i], wv, acc[v]);
        }
#pragma unroll
        for (int v = 0; v < 8; v++) g_bb2[(vbase + v) * 64 + o] = acc[v];
    }
}

// ---------------- K7: conv2 edge kernel (warp per edge, 2 outs/lane) --------
__global__ void k_conv2(const int* __restrict__ ei2, const float* __restrict__ w2a,
                        const float* __restrict__ b2a) {
    int e = (blockIdx.x * blockDim.x + threadIdx.x) >> 5;
    int lane = threadIdx.x & 31;
    if (e >= E2n) return;
    int src = ei2[e], dst = ei2[E2n + e];
    float inv = 0.5f / g_maxabs;
    float h = 0.f;
    if (lane < 25) {
        h = b2a[lane];
#pragma unroll
        for (int k = 0; k < 3; k++) {
            float cart = g_possum[src * 3 + k] - g_possum[dst * 3 + k];
            float eak = fmaf(cart, inv, 0.5f);
            h = fmaf(eak, w2a[k * 25 + lane], h);
        }
        h = fmaxf(h, 0.f);
    }
    const float* G = g_G2 + (size_t)src * 1600;
    float m0 = g_bb2[src * 64 + lane];
    float m1 = g_bb2[src * 64 + lane + 32];
#pragma unroll
    for (int r = 0; r < 25; r++) {
        float hr = __shfl_sync(0xffffffffu, h, r);
        m0 = fmaf(hr, G[r * 64 + lane], m0);
        m1 = fmaf(hr, G[r * 64 + lane + 32], m1);
    }
    atomicAdd(&g_sum2[dst * 64 + lane], m0);
    atomicAdd(&g_sum2[dst * 64 + lane + 32], m1);
    if (lane == 0) atomicAdd(&g_cnt2[dst], 1.f);
}

// ---------------- K8: node update 2 + pool2 scatter (warp per C1 node) ------
__global__ void k_node2(const int* __restrict__ cl2, const float* __restrict__ root2,
                        const float* __restrict__ bias2) {
    int c = (blockIdx.x * blockDim.x + threadIdx.x) >> 5;
    int lane = threadIdx.x & 31;
    if (c >= C1n) return;
    float cnt = fmaxf(g_cnt2[c], 1.f);
    float xpi = g_xp[c * 32 + lane];
    float v0 = g_sum2[c * 64 + lane] / cnt + bias2[lane];
    float v1 = g_sum2[c * 64 + lane + 32] / cnt + bias2[lane + 32];
#pragma unroll 8
    for (int i = 0; i < 32; i++) {
        float xi = __shfl_sync(0xffffffffu, xpi, i);
        v0 = fmaf(xi, root2[i * 64 + lane], v0);
        v1 = fmaf(xi, root2[i * 64 + lane + 32], v1);
    }
    float e0 = elu1(v0), e1 = elu1(v1);
    int c2 = cl2[c];
    atomicMaxFloat(&g_x3[c2 * 64 + lane], e0);
    atomicMaxFloat(&g_x3[c2 * 64 + lane + 32], e1);
    if (lane == 0) atomicMax(&g_batch2[c2], g_batchp[c]);
}

// ---------------- K9: pool2 finalize + global mean scatter -------------------
__global__ void k_pool2() {
    int c = (blockIdx.x * blockDim.x + threadIdx.x) >> 5;
    int lane = threadIdx.x & 31;
    if (c >= C2n) return;
    float v0 = g_x3[c * 64 + lane];      if (v0 < -3e38f) v0 = 0.f;
    float v1 = g_x3[c * 64 + lane + 32]; if (v1 < -3e38f) v1 = 0.f;
    int b = max(g_batch2[c], 0);
    atomicAdd(&g_gsum[b * 64 + lane], v0);
    atomicAdd(&g_gsum[b * 64 + lane + 32], v1);
    if (lane == 0) atomicAdd(&g_gcnt[b], 1.f);
}

// ---------------- K10: FC head + log_softmax (single block) ------------------
__global__ void k_head(const float* __restrict__ fc1w, const float* __restrict__ fc1b,
                       const float* __restrict__ fc2w, const float* __restrict__ fc2b,
                       float* __restrict__ out) {
    __shared__ float g[16 * 64];
    __shared__ float hh[16 * 128];
    __shared__ float lg[16 * 10];
    int tid = threadIdx.x;
    for (int i = tid; i < 16 * 64; i += 256) g[i] = g_gsum[i] / fmaxf(g_gcnt[i >> 6], 1.f);
    __syncthreads();
    for (int o = tid; o < 16 * 128; o += 256) {
        int b = o >> 7, j = o & 127;
        float acc = fc1b[j];
        for (int k = 0; k < 64; k++) acc = fmaf(g[b * 64 + k], fc1w[k * 128 + j], acc);
        hh[o] = elu1(acc);
    }
    __syncthreads();
    if (tid < 160) {
        int b = tid / 10, k = tid % 10;
        float acc = fc2b[k];
        for (int j = 0; j < 128; j++) acc = fmaf(hh[b * 128 + j], fc2w[j * 10 + k], acc);
        lg[tid] = acc;
    }
    __syncthreads();
    if (tid < 16) {
        float m = -1e30f;
        for (int k = 0; k < 10; k++) m = fmaxf(m, lg[tid * 10 + k]);
        float s = 0.f;
        for (int k = 0; k < 10; k++) s += expf(lg[tid * 10 + k] - m);
        float ls = logf(s) + m;
        for (int k = 0; k < 10; k++) out[tid * 10 + k] = lg[tid * 10 + k] - ls;
    }
}

// ---------------- host launcher ----------------------------------------------
extern "C" void kernel_launch(void* const* d_in, const int* in_sizes, int n_in,
                              void* d_out, int out_size) {
    const float *x, *ea, *pos, *w1a, *b1a, *w1b, *b1b, *root1, *bias1;
    const float *w2a, *b2a, *w2b, *b2b, *root2, *bias2, *fc1w, *fc1b, *fc2w, *fc2b;
    const int *ei, *batch, *cl1, *ei2, *cl2;

    if (in_sizes[3] == 2 * Ee) {
        // setup_inputs dict order
        x = (const float*)d_in[0];  ea = (const float*)d_in[1];  pos = (const float*)d_in[2];
        ei = (const int*)d_in[3];   batch = (const int*)d_in[4]; cl1 = (const int*)d_in[5];
        ei2 = (const int*)d_in[6];  cl2 = (const int*)d_in[7];
        w1a = (const float*)d_in[8];  b1a = (const float*)d_in[9];
        w1b = (const float*)d_in[10]; b1b = (const float*)d_in[11];
        root1 = (const float*)d_in[12]; bias1 = (const float*)d_in[13];
        w2a = (const float*)d_in[14]; b2a = (const float*)d_in[15];
        w2b = (const float*)d_in[16]; b2b = (const float*)d_in[17];
        root2 = (const float*)d_in[18]; bias2 = (const float*)d_in[19];
        fc1w = (const float*)d_in[20]; fc1b = (const float*)d_in[21];
        fc2w = (const float*)d_in[22]; fc2b = (const float*)d_in[23];
    } else {
        // reference() signature order
        x = (const float*)d_in[0];  ea = (const float*)d_in[1];  pos = (const float*)d_in[2];
        w1a = (const float*)d_in[3];  b1a = (const float*)d_in[4];
        w1b = (const float*)d_in[5];  b1b = (const float*)d_in[6];
        root1 = (const float*)d_in[7]; bias1 = (const float*)d_in[8];
        w2a = (const float*)d_in[9];  b2a = (const float*)d_in[10];
        w2b = (const float*)d_in[11]; b2b = (const float*)d_in[12];
        root2 = (const float*)d_in[13]; bias2 = (const float*)d_in[14];
        fc1w = (const float*)d_in[15]; fc1b = (const float*)d_in[16];
        fc2w = (const float*)d_in[17]; fc2b = (const float*)d_in[18];
        ei = (const int*)d_in[19];  batch = (const int*)d_in[20]; cl1 = (const int*)d_in[21];
        ei2 = (const int*)d_in[22]; cl2 = (const int*)d_in[23];
    }

    k_init<<<512, 256>>>();
    k_G1<<<(Nn * 32 + 255) / 256, 256>>>(x, w1b, b1b);
    k_conv1<<<(Ee * 32 + 255) / 256, 256>>>(ea, ei, w1a, b1a);
    k_node1<<<(Nn * 32 + 255) / 256, 256>>>(x, pos, batch, cl1, root1, bias1);
    k_pool1fix<<<(C1n * 32 + 255) / 256, 256>>>();
    k_maxabs<<<(E2n + 255) / 256, 256>>>(ei2);
    k_G2<<<C1n / 8, 256>>>(w2b, b2b);
    k_conv2<<<(E2n * 32 + 255) / 256, 256>>>(ei2, w2a, b2a);
    k_node2<<<(C1n * 32 + 255) / 256, 256>>>(cl2, root2, bias2);
    k_pool2<<<(C2n * 32 + 255) / 256, 256>>>();
    k_head<<<1, 256>>>(fc1w, fc1b, fc2w, fc2b, (float*)d_out);
}

// round 2
// speedup vs baseline: 1.2203x; 1.2203x over previous
#include <cuda_runtime.h>
#include <math.h>
#include <limits.h>

#define Nn 30000
#define Ee 400000
#define C1n 15000
#define E2n 100000
#define C2n 7500
#define Bn 16

// ---------------- scratch (device globals) -----------------------------------
__device__ int   g_deg1[Nn],  g_off1[Nn + 1],  g_cur1[Nn];     // CSR by src, conv1
__device__ int   g_degD1[Nn], g_offD1[Nn + 1], g_curD1[Nn];    // dst slots, conv1
__device__ int   g_deg2[C1n],  g_off2[C1n + 1],  g_cur2[C1n];  // CSR by src, conv2
__device__ int   g_degD2[C1n], g_offD2[C1n + 1], g_curD2[C1n]; // dst slots, conv2
__device__ int   g_csr1[Ee], g_posD1[Ee];
__device__ int   g_csr2[E2n], g_posD2[E2n];
__device__ int   g_cntc1[C1n];                                  // nodes per cluster1
__device__ float g_buf1[(size_t)Ee * 32];                       // per-edge msgs, dst order (51MB)
__device__ float g_buf2[(size_t)E2n * 64];                      // (26MB)
__device__ float g_xp[C1n * 32];
__device__ float g_possum[C1n * 3];
__device__ int   g_batchp[C1n];
__device__ float g_maxabs;
__device__ float g_G2[(size_t)C1n * 1600];                      // xp @ w2b (96MB)
__device__ float g_bb2[C1n * 64];
__device__ float g_x3[C2n * 64];
__device__ int   g_batch2[C2n];
__device__ float g_gsum[Bn * 64];
__device__ float g_gcnt[Bn];

__device__ __forceinline__ void atomicMaxFloat(float* addr, float val) {
    if (val >= 0.f) atomicMax((int*)addr, __float_as_int(val));
    else            atomicMin((unsigned int*)addr, __float_as_uint(val));
}
__device__ __forceinline__ float elu1(float v) { return v > 0.f ? v : expm1f(v); }

// ---------------- K0: init ----------------------------------------------------
__global__ void k_init() {
    int t = blockIdx.x * blockDim.x + threadIdx.x;
    int S = gridDim.x * blockDim.x;
    const float NEGINF = __int_as_float(0xff800000);
    for (int i = t; i < Nn; i += S) { g_deg1[i] = 0; g_degD1[i] = 0; }
    for (int i = t; i < C1n; i += S) { g_deg2[i] = 0; g_degD2[i] = 0; g_cntc1[i] = 0; g_batchp[i] = INT_MIN; }
    for (int i = t; i < C1n * 32; i += S) g_xp[i] = NEGINF;
    for (int i = t; i < C1n * 3; i += S)  g_possum[i] = 0.f;
    for (int i = t; i < C2n * 64; i += S) g_x3[i] = NEGINF;
    for (int i = t; i < C2n; i += S)      g_batch2[i] = INT_MIN;
    for (int i = t; i < Bn * 64; i += S)  g_gsum[i] = 0.f;
    for (int i = t; i < Bn; i += S)       g_gcnt[i] = 0.f;
    if (t == 0) g_maxabs = 0.f;
}

// ---------------- K1: degree histograms ---------------------------------------
__global__ void k_hist(const int* __restrict__ ei, const int* __restrict__ ei2,
                       const int* __restrict__ cl1) {
    int t = blockIdx.x * blockDim.x + threadIdx.x;
    int S = gridDim.x * blockDim.x;
    for (int e = t; e < Ee; e += S) {
        atomicAdd(&g_deg1[ei[e]], 1);
        atomicAdd(&g_degD1[ei[Ee + e]], 1);
    }
    for (int e = t; e < E2n; e += S) {
        atomicAdd(&g_deg2[ei2[e]], 1);
        atomicAdd(&g_degD2[ei2[E2n + e]], 1);
    }
    for (int n = t; n < Nn; n += S) atomicAdd(&g_cntc1[cl1[n]], 1);
}

// ---------------- K2: exclusive scans (4 arrays, 1 block each) ----------------
__global__ void k_scan() {
    const int* deg; int* off; int* cur; int n;
    switch (blockIdx.x) {
        case 0:  deg = g_deg1;  off = g_off1;  cur = g_cur1;  n = Nn;  break;
        case 1:  deg = g_degD1; off = g_offD1; cur = g_curD1; n = Nn;  break;
        case 2:  deg = g_deg2;  off = g_off2;  cur = g_cur2;  n = C1n; break;
        default: deg = g_degD2; off = g_offD2; cur = g_curD2; n = C1n; break;
    }
    __shared__ int wsum[32];
    __shared__ int carry;
    int tid = threadIdx.x, lane = tid & 31, wid = tid >> 5;
    if (tid == 0) carry = 0;
    __syncthreads();
    for (int base = 0; base < n; base += 1024) {
        int idx = base + tid;
        int v = (idx < n) ? deg[idx] : 0;
        int incl = v;
#pragma unroll
        for (int o = 1; o < 32; o <<= 1) {
            int tt = __shfl_up_sync(0xffffffffu, incl, o);
            if (lane >= o) incl += tt;
        }
        if (lane == 31) wsum[wid] = incl;
        __syncthreads();
        if (wid == 0) {
            int s = wsum[lane];
#pragma unroll
            for (int o = 1; o < 32; o <<= 1) {
                int tt = __shfl_up_sync(0xffffffffu, s, o);
                if (lane >= o) s += tt;
            }
            wsum[lane] = s;
        }
        __syncthreads();
        int woff = (wid == 0) ? 0 : wsum[wid - 1];
        int c0 = carry;
        if (idx < n) { int ex = c0 + woff + incl - v; off[idx] = ex; cur[idx] = ex; }
        __syncthreads();
        if (tid == 0) carry = c0 + wsum[31];
        __syncthreads();
    }
    if (threadIdx.x == 0) off[n] = carry;
}

// ---------------- K3: scatter edge ids / dst slots ----------------------------
__global__ void k_scat(const int* __restrict__ ei, const int* __restrict__ ei2) {
    int t = blockIdx.x * blockDim.x + threadIdx.x;
    int S = gridDim.x * blockDim.x;
    for (int e = t; e < Ee; e += S) {
        int p = atomicAdd(&g_cur1[ei[e]], 1);       g_csr1[p] = e;
        int q = atomicAdd(&g_curD1[ei[Ee + e]], 1); g_posD1[e] = q;
    }
    for (int e = t; e < E2n; e += S) {
        int p = atomicAdd(&g_cur2[ei2[e]], 1);        g_csr2[p] = e;
        int q = atomicAdd(&g_curD2[ei2[E2n + e]], 1); g_posD2[e] = q;
    }
}

// ---------------- K4: conv1 by src (fused G1, warp per node) ------------------
__global__ void k_conv1(const float* __restrict__ x, const float* __restrict__ ea,
                        const int* __restrict__ ei,
                        const float* __restrict__ w1a, const float* __restrict__ b1a,
                        const float* __restrict__ w1b, const float* __restrict__ b1b) {
    __shared__ __align__(16) float w1s[4800 + 192];
    int tid = threadIdx.x;
    // stage w1b (25x192) + b1b (192) into smem via float4
    {
        const float4* src4;
        for (int j = tid; j < 1248; j += 256) {
            float4 val;
            if (j < 1200) { src4 = (const float4*)w1b; val = src4[j]; }
            else          { src4 = (const float4*)b1b; val = src4[j - 1200]; }
            ((float4*)w1s)[j] = val;
        }
    }
    __syncthreads();
    int v = (blockIdx.x * blockDim.x + tid) >> 5;
    int lane = tid & 31;
    if (v >= Nn) return;
    float xv[6];
#pragma unroll
    for (int i = 0; i < 6; i++) xv[i] = x[v * 6 + i];
    float G[25];
#pragma unroll
    for (int r = 0; r < 25; r++) {
        float a = 0.f;
#pragma unroll
        for (int i = 0; i < 6; i++) a = fmaf(xv[i], w1s[r * 192 + i * 32 + lane], a);
        G[r] = a;
    }
    float bb = 0.f;
#pragma unroll
    for (int i = 0; i < 6; i++) bb = fmaf(xv[i], w1s[4800 + i * 32 + lane], bb);
    float wa0 = 0.f, wa1 = 0.f, wa2 = 0.f, ba = 0.f;
    if (lane < 25) { wa0 = w1a[lane]; wa1 = w1a[25 + lane]; wa2 = w1a[50 + lane]; ba = b1a[lane]; }
    int p0 = g_off1[v], p1 = g_off1[v + 1];
    for (int p = p0; p < p1; p++) {
        int e = g_csr1[p];
        int pd = g_posD1[e];
        float a0 = ea[3 * e], a1 = ea[3 * e + 1], a2 = ea[3 * e + 2];
        float h = fmaxf(fmaf(a0, wa0, fmaf(a1, wa1, fmaf(a2, wa2, ba))), 0.f);
        float msg = bb;
#pragma unroll
        for (int r = 0; r < 25; r++)
            msg = fmaf(__shfl_sync(0xffffffffu, h, r), G[r], msg);
        g_buf1[(size_t)pd * 32 + lane] = msg;
    }
}

// ---------------- K5: node1 = segment-mean(buf1) + root + elu + pool1 ---------
__global__ void k_node1(const float* __restrict__ x, const float* __restrict__ pos,
                        const int* __restrict__ batch, const int* __restrict__ cl1,
                        const float* __restrict__ root1, const float* __restrict__ bias1) {
    int n = (blockIdx.x * blockDim.x + threadIdx.x) >> 5;
    int lane = threadIdx.x & 31;
    if (n >= Nn) return;
    int p0 = g_offD1[n], p1 = g_offD1[n + 1];
    float acc = 0.f;
    for (int p = p0; p < p1; p++) acc += g_buf1[(size_t)p * 32 + lane];
    float v = acc / fmaxf((float)(p1 - p0), 1.f) + bias1[lane];
#pragma unroll
    for (int i = 0; i < 6; i++) v = fmaf(x[n * 6 + i], root1[i * 32 + lane], v);
    float x1 = elu1(v);
    int c = cl1[n];
    atomicMaxFloat(&g_xp[c * 32 + lane], x1);
    if (lane < 3) atomicAdd(&g_possum[c * 3 + lane], pos[n * 3 + lane]);
    if (lane == 0) atomicMax(&g_batchp[c], batch[n]);
}

// ---------------- K6: pool1 finalize ------------------------------------------
__global__ void k_pool1fix() {
    int c = (blockIdx.x * blockDim.x + threadIdx.x) >> 5;
    int lane = threadIdx.x & 31;
    if (c >= C1n) return;
    float v = g_xp[c * 32 + lane];
    if (v < -3e38f) g_xp[c * 32 + lane] = 0.f;
    if (lane < 3) g_possum[c * 3 + lane] = g_possum[c * 3 + lane] / fmaxf((float)g_cntc1[c], 1.f);
    if (lane == 0) g_batchp[c] = max(g_batchp[c], 0);
}

// ---------------- K7: global max |cart| ---------------------------------------
__global__ void k_maxabs(const int* __restrict__ ei2) {
    int e = blockIdx.x * blockDim.x + threadIdx.x;
    float m = 0.f;
    if (e < E2n) {
        int s = ei2[e], d = ei2[E2n + e];
#pragma unroll
        for (int k = 0; k < 3; k++)
            m = fmaxf(m, fabsf(g_possum[s * 3 + k] - g_possum[d * 3 + k]));
    }
#pragma unroll
    for (int o = 16; o; o >>= 1) m = fmaxf(m, __shfl_xor_sync(0xffffffffu, m, o));
    if ((threadIdx.x & 31) == 0) atomicMax((int*)&g_maxabs, __float_as_int(m));
}

// ---------------- K8: G2 = xp @ w2b, tiled GEMM -------------------------------
// grid (118 node tiles, 26): blockIdx.y = r-slice (25 = bias slice b2b)
__global__ void k_G2(const float* __restrict__ w2b, const float* __restrict__ b2b) {
    __shared__ __align__(16) float ws[2048];
    __shared__ __align__(16) float xst[32 * 132];   // [i][v], padded stride
    int tid = threadIdx.x;
    int vbase = blockIdx.x * 128;
    int rs = blockIdx.y;
    const float* wsrc = (rs < 25) ? (w2b + rs * 2048) : b2b;
    for (int j = tid; j < 512; j += 256) ((float4*)ws)[j] = ((const float4*)wsrc)[j];
    for (int idx = tid; idx < 128 * 32; idx += 256) {
        int v = idx >> 5, i = idx & 31;
        float val = (vbase + v < C1n) ? g_xp[(vbase + v) * 32 + i] : 0.f;
        xst[i * 132 + v] = val;
    }
    __syncthreads();
    int c4 = (tid & 15) * 4;   // col quad within 64
    int ng = tid >> 4;         // node group (8 nodes each)
    float acc[8][4];
#pragma unroll
    for (int n = 0; n < 8; n++)
#pragma unroll
        for (int c = 0; c < 4; c++) acc[n][c] = 0.f;
#pragma unroll 8
    for (int i = 0; i < 32; i++) {
        float4 w = *(const float4*)&ws[i * 64 + c4];
        float4 xa = *(const float4*)&xst[i * 132 + ng * 8];
        float4 xb = *(const float4*)&xst[i * 132 + ng * 8 + 4];
        float xv[8] = {xa.x, xa.y, xa.z, xa.w, xb.x, xb.y, xb.z, xb.w};
        float wv[4] = {w.x, w.y, w.z, w.w};
#pragma unroll
        for (int n = 0; n < 8; n++)
#pragma unroll
            for (int c = 0; c < 4; c++) acc[n][c] = fmaf(xv[n], wv[c], acc[n][c]);
    }
#pragma unroll
    for (int n = 0; n < 8; n++) {
        int v = vbase + ng * 8 + n;
        if (v < C1n) {
            float4 o = make_float4(acc[n][0], acc[n][1], acc[n][2], acc[n][3]);
            if (rs < 25) *(float4*)&g_G2[(size_t)v * 1600 + rs * 64 + c4] = o;
            else         *(float4*)&g_bb2[v * 64 + c4] = o;
        }
    }
}

// ---------------- K9: conv2 by src (warp per C1 node) -------------------------
__global__ void k_conv2(const int* __restrict__ ei2, const float* __restrict__ w2a,
                        const float* __restrict__ b2a) {
    int v = (blockIdx.x * blockDim.x + threadIdx.x) >> 5;
    int lane = threadIdx.x & 31;
    if (v >= C1n) return;
    float G0[25], G1[25];
    const float* G = g_G2 + (size_t)v * 1600;
#pragma unroll
    for (int r = 0; r < 25; r++) { G0[r] = G[r * 64 + lane]; G1[r] = G[r * 64 + 32 + lane]; }
    float bb0 = g_bb2[v * 64 + lane], bb1 = g_bb2[v * 64 + 32 + lane];
    float pv0 = g_possum[v * 3], pv1 = g_possum[v * 3 + 1], pv2 = g_possum[v * 3 + 2];
    float inv = 0.5f / g_maxabs;
    float wa0 = 0.f, wa1 = 0.f, wa2 = 0.f, ba = 0.f;
    if (lane < 25) { wa0 = w2a[lane]; wa1 = w2a[25 + lane]; wa2 = w2a[50 + lane]; ba = b2a[lane]; }
    int p0 = g_off2[v], p1 = g_off2[v + 1];
    for (int p = p0; p < p1; p++) {
        int e = g_csr2[p];
        int pd = g_posD2[e];
        int dst = ei2[E2n + e];
        float e0 = fmaf(pv0 - g_possum[dst * 3],     inv, 0.5f);
        float e1 = fmaf(pv1 - g_possum[dst * 3 + 1], inv, 0.5f);
        float e2 = fmaf(pv2 - g_possum[dst * 3 + 2], inv, 0.5f);
        float h = fmaxf(fmaf(e0, wa0, fmaf(e1, wa1, fmaf(e2, wa2, ba))), 0.f);
        float m0 = bb0, m1 = bb1;
#pragma unroll
        for (int r = 0; r < 25; r++) {
            float hr = __shfl_sync(0xffffffffu, h, r);
            m0 = fmaf(hr, G0[r], m0);
            m1 = fmaf(hr, G1[r], m1);
        }
        g_buf2[(size_t)pd * 64 + lane] = m0;
        g_buf2[(size_t)pd * 64 + 32 + lane] = m1;
    }
}

// ---------------- K10: node2 + pool2 scatter ----------------------------------
__global__ void k_node2(const int* __restrict__ cl2, const float* __restrict__ root2,
                        const float* __restrict__ bias2) {
    int c = (blockIdx.x * blockDim.x + threadIdx.x) >> 5;
    int lane = threadIdx.x & 31;
    if (c >= C1n) return;
    int p0 = g_offD2[c], p1 = g_offD2[c + 1];
    float a0 = 0.f, a1 = 0.f;
    for (int p = p0; p < p1; p++) {
        a0 += g_buf2[(size_t)p * 64 + lane];
        a1 += g_buf2[(size_t)p * 64 + 32 + lane];
    }
    float cnt = fmaxf((float)(p1 - p0), 1.f);
    float v0 = a0 / cnt + bias2[lane];
    float v1 = a1 / cnt + bias2[lane + 32];
    float xpi = g_xp[c * 32 + lane];
#pragma unroll 8
    for (int i = 0; i < 32; i++) {
        float xi = __shfl_sync(0xffffffffu, xpi, i);
        v0 = fmaf(xi, root2[i * 64 + lane], v0);
        v1 = fmaf(xi, root2[i * 64 + lane + 32], v1);
    }
    float e0 = elu1(v0), e1 = elu1(v1);
    int c2 = cl2[c];
    atomicMaxFloat(&g_x3[c2 * 64 + lane], e0);
    atomicMaxFloat(&g_x3[c2 * 64 + lane + 32], e1);
    if (lane == 0) atomicMax(&g_batch2[c2], g_batchp[c]);
}

// ---------------- K11: pool2 finalize + global mean scatter --------------------
__global__ void k_pool2() {
    int c = (blockIdx.x * blockDim.x + threadIdx.x) >> 5;
    int lane = threadIdx.x & 31;
    if (c >= C2n) return;
    float v0 = g_x3[c * 64 + lane];      if (v0 < -3e38f) v0 = 0.f;
    float v1 = g_x3[c * 64 + lane + 32]; if (v1 < -3e38f) v1 = 0.f;
    int b = max(g_batch2[c], 0);
    atomicAdd(&g_gsum[b * 64 + lane], v0);
    atomicAdd(&g_gsum[b * 64 + lane + 32], v1);
    if (lane == 0) atomicAdd(&g_gcnt[b], 1.f);
}

// ---------------- K12: FC head + log_softmax ----------------------------------
__global__ void k_head(const float* __restrict__ fc1w, const float* __restrict__ fc1b,
                       const float* __restrict__ fc2w, const float* __restrict__ fc2b,
                       float* __restrict__ out) {
    __shared__ float g[16 * 64];
    __shared__ float hh[16 * 128];
    __shared__ float lg[16 * 10];
    int tid = threadIdx.x;
    for (int i = tid; i < 16 * 64; i += 256) g[i] = g_gsum[i] / fmaxf(g_gcnt[i >> 6], 1.f);
    __syncthreads();
    for (int o = tid; o < 16 * 128; o += 256) {
        int b = o >> 7, j = o & 127;
        float acc = fc1b[j];
        for (int k = 0; k < 64; k++) acc = fmaf(g[b * 64 + k], fc1w[k * 128 + j], acc);
        hh[o] = elu1(acc);
    }
    __syncthreads();
    if (tid < 160) {
        int b = tid / 10, k = tid % 10;
        float acc = fc2b[k];
        for (int j = 0; j < 128; j++) acc = fmaf(hh[b * 128 + j], fc2w[j * 10 + k], acc);
        lg[tid] = acc;
    }
    __syncthreads();
    if (tid < 16) {
        float m = -1e30f;
        for (int k = 0; k < 10; k++) m = fmaxf(m, lg[tid * 10 + k]);
        float s = 0.f;
        for (int k = 0; k < 10; k++) s += expf(lg[tid * 10 + k] - m);
        float ls = logf(s) + m;
        for (int k = 0; k < 10; k++) out[tid * 10 + k] = lg[tid * 10 + k] - ls;
    }
}

// ---------------- host launcher -----------------------------------------------
extern "C" void kernel_launch(void* const* d_in, const int* in_sizes, int n_in,
                              void* d_out, int out_size) {
    const float *x, *ea, *pos, *w1a, *b1a, *w1b, *b1b, *root1, *bias1;
    const float *w2a, *b2a, *w2b, *b2b, *root2, *bias2, *fc1w, *fc1b, *fc2w, *fc2b;
    const int *ei, *batch, *cl1, *ei2, *cl2;

    if (in_sizes[3] == 2 * Ee) {
        x = (const float*)d_in[0];  ea = (const float*)d_in[1];  pos = (const float*)d_in[2];
        ei = (const int*)d_in[3];   batch = (const int*)d_in[4]; cl1 = (const int*)d_in[5];
        ei2 = (const int*)d_in[6];  cl2 = (const int*)d_in[7];
        w1a = (const float*)d_in[8];  b1a = (const float*)d_in[9];
        w1b = (const float*)d_in[10]; b1b = (const float*)d_in[11];
        root1 = (const float*)d_in[12]; bias1 = (const float*)d_in[13];
        w2a = (const float*)d_in[14]; b2a = (const float*)d_in[15];
        w2b = (const float*)d_in[16]; b2b = (const float*)d_in[17];
        root2 = (const float*)d_in[18]; bias2 = (const float*)d_in[19];
        fc1w = (const float*)d_in[20]; fc1b = (const float*)d_in[21];
        fc2w = (const float*)d_in[22]; fc2b = (const float*)d_in[23];
    } else {
        x = (const float*)d_in[0];  ea = (const float*)d_in[1];  pos = (const float*)d_in[2];
        w1a = (const float*)d_in[3];  b1a = (const float*)d_in[4];
        w1b = (const float*)d_in[5];  b1b = (const float*)d_in[6];
        root1 = (const float*)d_in[7]; bias1 = (const float*)d_in[8];
        w2a = (const float*)d_in[9];  b2a = (const float*)d_in[10];
        w2b = (const float*)d_in[11]; b2b = (const float*)d_in[12];
        root2 = (const float*)d_in[13]; bias2 = (const float*)d_in[14];
        fc1w = (const float*)d_in[15]; fc1b = (const float*)d_in[16];
        fc2w = (const float*)d_in[17]; fc2b = (const float*)d_in[18];
        ei = (const int*)d_in[19];  batch = (const int*)d_in[20]; cl1 = (const int*)d_in[21];
        ei2 = (const int*)d_in[22]; cl2 = (const int*)d_in[23];
    }

    k_init<<<256, 256>>>();
    k_hist<<<256, 256>>>(ei, ei2, cl1);
    k_scan<<<4, 1024>>>();
    k_scat<<<256, 256>>>(ei, ei2);
    k_conv1<<<3750, 256>>>(x, ea, ei, w1a, b1a, w1b, b1b);
    k_node1<<<3750, 256>>>(x, pos, batch, cl1, root1, bias1);
    k_pool1fix<<<1875, 256>>>();
    k_maxabs<<<(E2n + 255) / 256, 256>>>(ei2);
    k_G2<<<dim3(118, 26), 256>>>(w2b, b2b);
    k_conv2<<<1875, 256>>>(ei2, w2a, b2a);
    k_node2<<<1875, 256>>>(cl2, root2, bias2);
    k_pool2<<<938, 256>>>();
    k_head<<<1, 256>>>(fc1w, fc1b, fc2w, fc2b, (float*)d_out);
}